// round 6
// baseline (speedup 1.0000x reference)
#include <cuda_runtime.h>
#include <cstdint>
#include <cstddef>

#define B_      64
#define LQ      1024
#define LK      1024
#define DH      64
#define QT      8
#define CHUNK   256
#define NCH     (LK / CHUNK)   // 4
#define NTHR    512
#define KSP     68             // k_s pitch: (r*68+c)%32 = (4r+c)%32 -> conflict-free A-frag LDS
#define SCP     1028           // sc pitch: 1028%32=4 -> score STS banks 8c+r, conflict-free
#define TEMP_INV 0.125f
#define REMOVED  (-1.0e30f)
#define CUTV     (-1.0e29f)

// smem floats: k_s[256*68] | sc[8*1028] | tau_s[8] | part[8*64]
#define KS_FLOATS   (CHUNK * KSP)
#define SC_FLOATS   (QT * SCP)
#define SMEM_FLOATS (KS_FLOATS + SC_FLOATS + 8 + QT * 64)
#define SMEM_BYTES  (SMEM_FLOATS * 4)

__device__ int g_mask_kind;   // 0 = uint8/bool, 1 = int32, 2 = float32

__global__ void detect_mask_kernel(const unsigned char* __restrict__ m) {
    __shared__ int nz[4];
    int tid = threadIdx.x;
    if (tid < 4) nz[tid] = 0;
    __syncthreads();
    int ph = tid & 3;
    int c = 0;
    for (int i = tid; i < 16384; i += 256)
        if (m[i]) c++;
    if (c) atomicAdd(&nz[ph], c);
    __syncthreads();
    if (tid == 0) {
        int kind;
        if ((nz[1] | nz[2] | nz[3]) == 0)      kind = 1;  // int32
        else if (nz[0] == 0 && nz[3] > 0)      kind = 2;  // float32
        else                                   kind = 0;  // uint8 / bool
        g_mask_kind = kind;
    }
}

// Markidis truncation split: hi = x with low 13 mantissa bits cleared (valid tf32),
// lo = x - hi (exact, also a valid tf32 operand).
__device__ __forceinline__ float trunc_hi(float x) {
    return __uint_as_float(__float_as_uint(x) & 0xFFFFE000u);
}

__device__ __forceinline__ void mma_tf32(float& d0, float& d1, float& d2, float& d3,
                                         unsigned a0, unsigned a1, unsigned a2, unsigned a3,
                                         unsigned b0, unsigned b1) {
    asm("mma.sync.aligned.m16n8k8.row.col.f32.tf32.tf32.f32 "
        "{%0,%1,%2,%3}, {%4,%5,%6,%7}, {%8,%9}, {%0,%1,%2,%3};"
        : "+f"(d0), "+f"(d1), "+f"(d2), "+f"(d3)
        : "r"(a0), "r"(a1), "r"(a2), "r"(a3), "r"(b0), "r"(b1));
}

// --------------------------------------------------------------------------
// One CTA = 8 q-rows of one batch, 512 threads / 16 warps.
// GEMM (roles swapped): A = K 16-row slice (smem, scalar LDS), B = Q tile
// (registers, hi/lo tf32 split, 32 regs). Warp w owns k-rows [16w,16w+16) of
// each 256-wide chunk; output tile = 16k x 8q per chunk.
// Sparsemax: warps 0-7 find tau (stateless Michelot rescan); all 16 warps
// then split the sparse attn@V gather (2 warps per row).
// --------------------------------------------------------------------------
extern "C" __global__ void __launch_bounds__(NTHR, 2)
sparse_attn_kernel(const float* __restrict__ q,
                   const float* __restrict__ k,
                   const float* __restrict__ v,
                   const void*  __restrict__ maskp,
                   float* __restrict__ out,
                   float* __restrict__ attn,
                   int write_attn)
{
    extern __shared__ float sm[];
    float* k_s   = sm;                            // [CHUNK][KSP]
    float* sc    = sm + KS_FLOATS;                // [QT][SCP]
    float* tau_s = sc + SC_FLOATS;                // [QT]
    float* part  = tau_s + 8;                     // [QT][64]

    const int tid  = threadIdx.x;
    const int w    = tid >> 5;
    const int lane = tid & 31;
    const int b    = blockIdx.y;
    const int q0   = blockIdx.x * QT;
    const int mkind = g_mask_kind;

    // ---- Q tile as B fragments in registers (hi/lo tf32 split) ----
    // col-major B[d][n]: b0 = Q[q0 + lane/4][ks*8 + lane%4], b1 at d+4
    unsigned bh0[8], bh1[8], bl0[8], bl1[8];
    {
        const float* qb = q + ((size_t)(b * LQ + q0 + (lane >> 2))) * DH + (lane & 3);
        #pragma unroll
        for (int ks = 0; ks < 8; ++ks) {
            float x0 = qb[ks * 8]     * TEMP_INV;
            float x1 = qb[ks * 8 + 4] * TEMP_INV;
            float h0 = trunc_hi(x0), h1 = trunc_hi(x1);
            bh0[ks] = __float_as_uint(h0);  bl0[ks] = __float_as_uint(x0 - h0);
            bh1[ks] = __float_as_uint(h1);  bl1[ks] = __float_as_uint(x1 - h1);
        }
    }

    // ---- QK^T over 4 chunks of 256 K-rows ----
    for (int c = 0; c < NCH; ++c) {
        __syncthreads();
        // stage K chunk: 256 rows x 16 float4, coalesced
        #pragma unroll
        for (int it = 0; it < (CHUNK * 16) / NTHR; ++it) {
            int fi = tid + NTHR * it;
            int r  = fi >> 4;
            int d4 = fi & 15;
            const float4 kv = *(const float4*)(k + ((size_t)(b * LK + c * CHUNK + r)) * DH + 4 * d4);
            *(float4*)(k_s + r * KSP + 4 * d4) = kv;
        }
        __syncthreads();

        // A = K rows [w*16, w*16+16): a0=(r,cd) a1=(r+8,cd) a2=(r,cd+4) a3=(r+8,cd+4)
        float d0 = 0.f, d1 = 0.f, d2 = 0.f, d3 = 0.f;
        const float* ap = k_s + (w * 16 + (lane >> 2)) * KSP + (lane & 3);
        #pragma unroll
        for (int ks = 0; ks < 8; ++ks) {
            float a0f = ap[ks * 8];
            float a1f = ap[8 * KSP + ks * 8];
            float a2f = ap[ks * 8 + 4];
            float a3f = ap[8 * KSP + ks * 8 + 4];
            float h0 = trunc_hi(a0f), h1 = trunc_hi(a1f), h2 = trunc_hi(a2f), h3 = trunc_hi(a3f);
            unsigned ah0 = __float_as_uint(h0), ah1 = __float_as_uint(h1),
                     ah2 = __float_as_uint(h2), ah3 = __float_as_uint(h3);
            unsigned al0 = __float_as_uint(a0f - h0), al1 = __float_as_uint(a1f - h1),
                     al2 = __float_as_uint(a2f - h2), al3 = __float_as_uint(a3f - h3);
            mma_tf32(d0, d1, d2, d3, ah0, ah1, ah2, ah3, bl0[ks], bl1[ks]);
            mma_tf32(d0, d1, d2, d3, al0, al1, al2, al3, bh0[ks], bh1[ks]);
            mma_tf32(d0, d1, d2, d3, ah0, ah1, ah2, ah3, bh0[ks], bh1[ks]);
        }
        // C: c0=(kr, 2qc) c1=(kr, 2qc+1) c2=(kr+8, 2qc) c3=(kr+8, 2qc+1); scores in sc[q][k]
        int kg = c * CHUNK + w * 16 + (lane >> 2);
        int qc = 2 * (lane & 3);
        sc[qc * SCP + kg]           = d0;
        sc[(qc + 1) * SCP + kg]     = d1;
        sc[qc * SCP + kg + 8]       = d2;
        sc[(qc + 1) * SCP + kg + 8] = d3;
    }
    __syncthreads();

    // ---- mask pass, 16-byte vectorized ----
    {
        size_t mbase = ((size_t)b * LQ + q0) * LK;
        if (mkind == 0) {
            const uint4* m4 = (const uint4*)((const unsigned char*)maskp + mbase);
            {
                int idx  = tid;                       // (8*1024)/16 == 512 == NTHR
                uint4 u  = m4[idx];
                int base = idx * 16;
                float* srow = sc + (base >> 10) * SCP + (base & 1023);
                #pragma unroll
                for (int bt = 0; bt < 4; ++bt) {
                    unsigned uu = (&u.x)[bt];
                    if (uu & 0x000000FFu) srow[bt * 4 + 0] = REMOVED;
                    if (uu & 0x0000FF00u) srow[bt * 4 + 1] = REMOVED;
                    if (uu & 0x00FF0000u) srow[bt * 4 + 2] = REMOVED;
                    if (uu & 0xFF000000u) srow[bt * 4 + 3] = REMOVED;
                }
            }
        } else {   // int32 / float32: nonzero bits == true
            const uint4* m4 = (const uint4*)((const unsigned*)maskp + mbase);
            #pragma unroll
            for (int it = 0; it < (QT * LK) / 4 / NTHR; ++it) {
                int idx  = tid + NTHR * it;
                uint4 u  = m4[idx];
                int base = idx * 4;
                float* srow = sc + (base >> 10) * SCP + (base & 1023);
                if (u.x) srow[0] = REMOVED;
                if (u.y) srow[1] = REMOVED;
                if (u.z) srow[2] = REMOVED;
                if (u.w) srow[3] = REMOVED;
            }
        }
    }
    __syncthreads();

    // ---- sparsemax tau (warps 0-7, row = w): stateless Michelot ----
    if (w < QT) {
        const float* zr = sc + w * SCP;
        float S = 0.0f; int C = 0;
        #pragma unroll
        for (int t4 = 0; t4 < 8; ++t4) {
            float4 zv = *(const float4*)(zr + 4 * lane + 128 * t4);
            if (zv.x > CUTV) { S += zv.x; C++; }
            if (zv.y > CUTV) { S += zv.y; C++; }
            if (zv.z > CUTV) { S += zv.z; C++; }
            if (zv.w > CUTV) { S += zv.w; C++; }
        }
        #pragma unroll
        for (int o = 16; o; o >>= 1) {
            S += __shfl_xor_sync(0xFFFFFFFFu, S, o);
            C += __shfl_xor_sync(0xFFFFFFFFu, C, o);
        }

        float tau;
        if (C > 0) {
            tau = (S - 1.0f) / (float)C;
            for (int iter = 0; iter < 64; ++iter) {
                float s2 = 0.0f; int c2 = 0;
                #pragma unroll
                for (int t4 = 0; t4 < 8; ++t4) {
                    float4 zv = *(const float4*)(zr + 4 * lane + 128 * t4);
                    if (zv.x > tau) { s2 += zv.x; c2++; }
                    if (zv.y > tau) { s2 += zv.y; c2++; }
                    if (zv.z > tau) { s2 += zv.z; c2++; }
                    if (zv.w > tau) { s2 += zv.w; c2++; }
                }
                #pragma unroll
                for (int o = 16; o; o >>= 1) {
                    s2 += __shfl_xor_sync(0xFFFFFFFFu, s2, o);
                    c2 += __shfl_xor_sync(0xFFFFFFFFu, c2, o);
                }
                if (c2 == C) break;        // converged
                S = s2; C = c2;
                tau = (S - 1.0f) / (float)C;
            }
        } else {
            tau = 1.0e30f;                 // fully-masked row
        }
        if (lane == 0) tau_s[w] = tau;
    }
    __syncthreads();

    // ---- probabilities + sparse attn@V: 2 warps per row (halves of k-range) ----
    {
        const int row  = w & 7;
        const int half = w >> 3;
        const float tau = tau_s[row];
        const float* zr = sc + row * SCP;
        const float* vb = v + (size_t)b * LK * DH;
        float* arow = attn + ((size_t)(b * LQ + q0 + row)) * LK;

        float2 acc2 = make_float2(0.0f, 0.0f);
        #pragma unroll
        for (int tt = 0; tt < 16; ++tt) {
            int t = half * 16 + tt;
            float p = fmaxf(zr[lane + 32 * t] - tau, 0.0f);
            if (write_attn) arow[lane + 32 * t] = p;
            unsigned bal = __ballot_sync(0xFFFFFFFFu, p > 0.0f);
            while (bal) {
                int src = __ffs(bal) - 1;
                bal &= bal - 1;
                float pj = __shfl_sync(0xFFFFFFFFu, p, src);
                int j = src + 32 * t;
                const float2 vv = *(const float2*)(vb + (size_t)j * DH + 2 * lane);
                acc2.x += pj * vv.x;
                acc2.y += pj * vv.y;
            }
        }
        if (half == 0) {
            part[row * 64 + 2 * lane]     = acc2.x;
            part[row * 64 + 2 * lane + 1] = acc2.y;
        }
        __syncthreads();
        if (half == 1) {
            acc2.x += part[row * 64 + 2 * lane];
            acc2.y += part[row * 64 + 2 * lane + 1];
            *(float2*)(out + ((size_t)(b * LQ + q0 + row)) * DH + 2 * lane) = acc2;
        }
    }
}

// --------------------------------------------------------------------------
extern "C" void kernel_launch(void* const* d_in, const int* in_sizes, int n_in,
                              void* d_out, int out_size) {
    const float* q = (const float*)d_in[0];
    const float* k = (const float*)d_in[1];
    const float* v = (const float*)d_in[2];
    const void*  m = d_in[3];

    float* out = (float*)d_out;
    long long out_elems  = (long long)B_ * LQ * DH;
    long long attn_elems = (long long)B_ * LQ * LK;
    int write_attn = ((long long)out_size >= out_elems + attn_elems) ? 1 : 0;
    float* attn = out + (size_t)out_elems;

    detect_mask_kernel<<<1, 256>>>((const unsigned char*)m);

    cudaFuncSetAttribute(sparse_attn_kernel,
                         cudaFuncAttributeMaxDynamicSharedMemorySize, SMEM_BYTES);

    dim3 grid(LQ / QT, B_);
    sparse_attn_kernel<<<grid, NTHR, SMEM_BYTES>>>(q, k, v, m, out, attn, write_attn);
}

// round 7
// speedup vs baseline: 1.2930x; 1.2930x over previous
#include <cuda_runtime.h>
#include <cstdint>
#include <cstddef>

#define B_      64
#define LQ      1024
#define LK      1024
#define DH      64
#define QT      16
#define CHUNK   128
#define NCH     (LK / CHUNK)   // 8
#define NTHR    512
#define KSP     68             // k_s pitch: banks (4r+c)%32 -> conflict-free A-frag LDS
#define SCP     1028           // sc pitch: score STS banks 8c+r -> conflict-free
#define TEMP_INV 0.125f
#define REMOVED  (-1.0e30f)
#define CUTV     (-1.0e29f)

// smem floats: k_s[128*68] | sc[16*1028]
#define KS_FLOATS   (CHUNK * KSP)
#define SC_FLOATS   (QT * SCP)
#define SMEM_FLOATS (KS_FLOATS + SC_FLOATS)
#define SMEM_BYTES  (SMEM_FLOATS * 4)

__device__ int g_mask_kind;   // 0 = uint8/bool, 1 = int32, 2 = float32

__global__ void detect_mask_kernel(const unsigned char* __restrict__ m) {
    __shared__ int nz[4];
    int tid = threadIdx.x;
    if (tid < 4) nz[tid] = 0;
    __syncthreads();
    int ph = tid & 3;
    int c = 0;
    for (int i = tid; i < 16384; i += 256)
        if (m[i]) c++;
    if (c) atomicAdd(&nz[ph], c);
    __syncthreads();
    if (tid == 0) {
        int kind;
        if ((nz[1] | nz[2] | nz[3]) == 0)      kind = 1;  // int32
        else if (nz[0] == 0 && nz[3] > 0)      kind = 2;  // float32
        else                                   kind = 0;  // uint8 / bool
        g_mask_kind = kind;
    }
}

// Markidis truncation split: hi = x with low 13 mantissa bits cleared (valid tf32),
// lo = x - hi (exact, also a valid tf32 operand).
__device__ __forceinline__ float trunc_hi(float x) {
    return __uint_as_float(__float_as_uint(x) & 0xFFFFE000u);
}

__device__ __forceinline__ void mma_tf32(float& d0, float& d1, float& d2, float& d3,
                                         unsigned a0, unsigned a1, unsigned a2, unsigned a3,
                                         unsigned b0, unsigned b1) {
    asm("mma.sync.aligned.m16n8k8.row.col.f32.tf32.tf32.f32 "
        "{%0,%1,%2,%3}, {%4,%5,%6,%7}, {%8,%9}, {%0,%1,%2,%3};"
        : "+f"(d0), "+f"(d1), "+f"(d2), "+f"(d3)
        : "r"(a0), "r"(a1), "r"(a2), "r"(a3), "r"(b0), "r"(b1));
}

// --------------------------------------------------------------------------
// One CTA = 16 q-rows of one batch, 512 threads / 16 warps.
// GEMM: A = K (smem, scalar LDS), B = Q (16 fp32 regs/warp, split inline).
// Per 128-wide chunk, warp w computes the 16k x 8q tile at
// k-rows [16*(w&7), +16), q-subtile (w>>3). No smem A-fragment table.
// Sparsemax/attn/V: warp w owns score row w (stateless Michelot rescan).
// --------------------------------------------------------------------------
extern "C" __global__ void __launch_bounds__(NTHR, 2)
sparse_attn_kernel(const float* __restrict__ q,
                   const float* __restrict__ k,
                   const float* __restrict__ v,
                   const void*  __restrict__ maskp,
                   float* __restrict__ out,
                   float* __restrict__ attn,
                   int write_attn)
{
    extern __shared__ float sm[];
    float* k_s = sm;                              // [CHUNK][KSP]
    float* sc  = sm + KS_FLOATS;                  // [QT][SCP]

    const int tid  = threadIdx.x;
    const int w    = tid >> 5;
    const int lane = tid & 31;
    const int b    = blockIdx.y;
    const int q0   = blockIdx.x * QT;
    const int mkind = g_mask_kind;

    // ---- Q subtile (w>>3) as fp32 B-fragment values in registers ----
    // b0 = Q[q0 + 8*(w>>3) + lane/4][ks*8 + lane%4], b1 at d+4
    float x0[8], x1[8];
    {
        const float* qb = q + ((size_t)(b * LQ + q0 + 8 * (w >> 3) + (lane >> 2))) * DH + (lane & 3);
        #pragma unroll
        for (int ks = 0; ks < 8; ++ks) {
            x0[ks] = qb[ks * 8]     * TEMP_INV;
            x1[ks] = qb[ks * 8 + 4] * TEMP_INV;
        }
    }
    const int kr0 = 16 * (w & 7);

    // ---- QK^T over 8 chunks of 128 K-rows ----
    for (int c = 0; c < NCH; ++c) {
        __syncthreads();
        // stage K chunk: 128 rows x 16 float4, coalesced
        #pragma unroll
        for (int it = 0; it < (CHUNK * 16) / NTHR; ++it) {
            int fi = tid + NTHR * it;
            int r  = fi >> 4;
            int d4 = fi & 15;
            const float4 kv = *(const float4*)(k + ((size_t)(b * LK + c * CHUNK + r)) * DH + 4 * d4);
            *(float4*)(k_s + r * KSP + 4 * d4) = kv;
        }
        __syncthreads();

        // A = K rows [kr0, kr0+16): a0=(r,cd) a1=(r+8,cd) a2=(r,cd+4) a3=(r+8,cd+4)
        float d0 = 0.f, d1 = 0.f, d2 = 0.f, d3 = 0.f;
        const float* ap = k_s + (kr0 + (lane >> 2)) * KSP + (lane & 3);
        #pragma unroll
        for (int ks = 0; ks < 8; ++ks) {
            float a0f = ap[ks * 8];
            float a1f = ap[8 * KSP + ks * 8];
            float a2f = ap[ks * 8 + 4];
            float a3f = ap[8 * KSP + ks * 8 + 4];
            float h0 = trunc_hi(a0f), h1 = trunc_hi(a1f), h2 = trunc_hi(a2f), h3 = trunc_hi(a3f);
            unsigned ah0 = __float_as_uint(h0), ah1 = __float_as_uint(h1),
                     ah2 = __float_as_uint(h2), ah3 = __float_as_uint(h3);
            unsigned al0 = __float_as_uint(a0f - h0), al1 = __float_as_uint(a1f - h1),
                     al2 = __float_as_uint(a2f - h2), al3 = __float_as_uint(a3f - h3);
            float qh0f = trunc_hi(x0[ks]), qh1f = trunc_hi(x1[ks]);
            unsigned qh0 = __float_as_uint(qh0f), qh1 = __float_as_uint(qh1f);
            unsigned ql0 = __float_as_uint(x0[ks] - qh0f), ql1 = __float_as_uint(x1[ks] - qh1f);
            mma_tf32(d0, d1, d2, d3, ah0, ah1, ah2, ah3, ql0, ql1);
            mma_tf32(d0, d1, d2, d3, al0, al1, al2, al3, qh0, qh1);
            mma_tf32(d0, d1, d2, d3, ah0, ah1, ah2, ah3, qh0, qh1);
        }
        // C: c0=(kr, qc) c1=(kr, qc+1) c2=(kr+8, qc) c3=(kr+8, qc+1); scores in sc[q][k]
        int kg = c * CHUNK + kr0 + (lane >> 2);
        int qc = 8 * (w >> 3) + 2 * (lane & 3);
        sc[qc * SCP + kg]           = d0;
        sc[(qc + 1) * SCP + kg]     = d1;
        sc[qc * SCP + kg + 8]       = d2;
        sc[(qc + 1) * SCP + kg + 8] = d3;
    }
    __syncthreads();

    // ---- mask pass, 16-byte vectorized ----
    {
        size_t mbase = ((size_t)b * LQ + q0) * LK;
        if (mkind == 0) {
            const uint4* m4 = (const uint4*)((const unsigned char*)maskp + mbase);
            #pragma unroll
            for (int it = 0; it < (QT * LK) / 16 / NTHR; ++it) {
                int idx  = tid + NTHR * it;
                uint4 u  = m4[idx];
                int base = idx * 16;
                float* srow = sc + (base >> 10) * SCP + (base & 1023);
                #pragma unroll
                for (int bt = 0; bt < 4; ++bt) {
                    unsigned uu = (&u.x)[bt];
                    if (uu & 0x000000FFu) srow[bt * 4 + 0] = REMOVED;
                    if (uu & 0x0000FF00u) srow[bt * 4 + 1] = REMOVED;
                    if (uu & 0x00FF0000u) srow[bt * 4 + 2] = REMOVED;
                    if (uu & 0xFF000000u) srow[bt * 4 + 3] = REMOVED;
                }
            }
        } else {   // int32 / float32: nonzero bits == true
            const uint4* m4 = (const uint4*)((const unsigned*)maskp + mbase);
            #pragma unroll
            for (int it = 0; it < (QT * LK) / 4 / NTHR; ++it) {
                int idx  = tid + NTHR * it;
                uint4 u  = m4[idx];
                int base = idx * 4;
                float* srow = sc + (base >> 10) * SCP + (base & 1023);
                if (u.x) srow[0] = REMOVED;
                if (u.y) srow[1] = REMOVED;
                if (u.z) srow[2] = REMOVED;
                if (u.w) srow[3] = REMOVED;
            }
        }
    }
    __syncthreads();

    // ---- sparsemax (warp w owns row w): stateless Michelot ----
    const float* zr = sc + w * SCP;
    float S = 0.0f; int C = 0;
    #pragma unroll
    for (int t4 = 0; t4 < 8; ++t4) {
        float4 zv = *(const float4*)(zr + 4 * lane + 128 * t4);
        if (zv.x > CUTV) { S += zv.x; C++; }
        if (zv.y > CUTV) { S += zv.y; C++; }
        if (zv.z > CUTV) { S += zv.z; C++; }
        if (zv.w > CUTV) { S += zv.w; C++; }
    }
    #pragma unroll
    for (int o = 16; o; o >>= 1) {
        S += __shfl_xor_sync(0xFFFFFFFFu, S, o);
        C += __shfl_xor_sync(0xFFFFFFFFu, C, o);
    }

    float tau;
    if (C > 0) {
        tau = (S - 1.0f) / (float)C;
        for (int iter = 0; iter < 64; ++iter) {
            float s2 = 0.0f; int c2 = 0;
            #pragma unroll
            for (int t4 = 0; t4 < 8; ++t4) {
                float4 zv = *(const float4*)(zr + 4 * lane + 128 * t4);
                if (zv.x > tau) { s2 += zv.x; c2++; }
                if (zv.y > tau) { s2 += zv.y; c2++; }
                if (zv.z > tau) { s2 += zv.z; c2++; }
                if (zv.w > tau) { s2 += zv.w; c2++; }
            }
            #pragma unroll
            for (int o = 16; o; o >>= 1) {
                s2 += __shfl_xor_sync(0xFFFFFFFFu, s2, o);
                c2 += __shfl_xor_sync(0xFFFFFFFFu, c2, o);
            }
            if (c2 == C) break;            // converged
            S = s2; C = c2;
            tau = (S - 1.0f) / (float)C;
        }
    } else {
        tau = 1.0e30f;                     // fully-masked row
    }

    // ---- probabilities -> attn (direct) + sparse attn@V ----
    const float* vb = v + (size_t)b * LK * DH;
    float2 acc2 = make_float2(0.0f, 0.0f);
    float* arow = attn + ((size_t)(b * LQ + q0 + w)) * LK;
    #pragma unroll
    for (int t = 0; t < 32; ++t) {
        float p = fmaxf(zr[lane + 32 * t] - tau, 0.0f);
        if (write_attn) arow[lane + 32 * t] = p;
        unsigned bal = __ballot_sync(0xFFFFFFFFu, p > 0.0f);
        while (bal) {
            int src = __ffs(bal) - 1;
            bal &= bal - 1;
            float pj = __shfl_sync(0xFFFFFFFFu, p, src);
            int j = src + 32 * t;
            const float2 vv = *(const float2*)(vb + (size_t)j * DH + 2 * lane);
            acc2.x += pj * vv.x;
            acc2.y += pj * vv.y;
        }
    }
    *(float2*)(out + ((size_t)(b * LQ + q0 + w)) * DH + 2 * lane) = acc2;
}

// --------------------------------------------------------------------------
extern "C" void kernel_launch(void* const* d_in, const int* in_sizes, int n_in,
                              void* d_out, int out_size) {
    const float* q = (const float*)d_in[0];
    const float* k = (const float*)d_in[1];
    const float* v = (const float*)d_in[2];
    const void*  m = d_in[3];

    float* out = (float*)d_out;
    long long out_elems  = (long long)B_ * LQ * DH;
    long long attn_elems = (long long)B_ * LQ * LK;
    int write_attn = ((long long)out_size >= out_elems + attn_elems) ? 1 : 0;
    float* attn = out + (size_t)out_elems;

    detect_mask_kernel<<<1, 256>>>((const unsigned char*)m);

    cudaFuncSetAttribute(sparse_attn_kernel,
                         cudaFuncAttributeMaxDynamicSharedMemorySize, SMEM_BYTES);

    dim3 grid(LQ / QT, B_);
    sparse_attn_kernel<<<grid, NTHR, SMEM_BYTES>>>(q, k, v, m, out, attn, write_attn);
}